// round 12
// baseline (speedup 1.0000x reference)
#include <cuda_runtime.h>
#include <cuda_bf16.h>
#include <math.h>
#include <stdint.h>

#define NND    6144
#define NFEAT  512
#define NHID   256
#define NCLASS 8
#define ADIM   128
#define NTILES 48

typedef __nv_bfloat16 bf16;

// ---------------- device scratch (no allocations allowed) ----------------
__device__ float g_nzT[3 * NND];
__device__ float g_wfold[3 * NND * 4];
__device__ float g_bfold[3];
__device__ float g_part[3 * (size_t)NND * NHID];
__device__ float g_xtw2[NND * NCLASS];
__device__ float g_Mt[NTILES * NND];
__device__ float g_Lt[NTILES * NND];
__device__ float g_rowM[NND];
__device__ float g_rowInvL[NND];

__device__ bf16 g_adjH[(size_t)NND * NND],   g_adjL[(size_t)NND * NND];
__device__ bf16 g_attH[(size_t)NND * NND],   g_attL[(size_t)NND * NND];   // logits H/L
__device__ bf16 g_featsH[(size_t)NND * NFEAT], g_featsL[(size_t)NND * NFEAT];
__device__ bf16 g_W1TH[NHID * NFEAT],  g_W1TL[NHID * NFEAT];
__device__ bf16 g_WqTH[NHID * NHID],   g_WqTL[NHID * NHID];
__device__ bf16 g_WkTH[NHID * NHID],   g_WkTL[NHID * NHID];
__device__ bf16 g_WvTH[NHID * NHID],   g_WvTL[NHID * NHID];
__device__ bf16 g_fW1TH[(size_t)NHID * NND], g_fW1TL[(size_t)NHID * NND];
__device__ bf16 g_xH[(size_t)NND * NHID],  g_xL[(size_t)NND * NHID];
__device__ bf16 g_QH[(size_t)NND * NHID],  g_QL[(size_t)NND * NHID];
__device__ bf16 g_KHb[(size_t)NND * NHID], g_KLb[(size_t)NND * NHID];
__device__ bf16 g_VTH[(size_t)NHID * NND], g_VTL[(size_t)NHID * NND];

// ---------------- helpers ----------------
__device__ __forceinline__ uint32_t s2u(const void* p) {
    uint32_t a;
    asm("{ .reg .u64 t; cvta.to.shared.u64 t, %1; cvt.u32.u64 %0, t; }" : "=r"(a) : "l"(p));
    return a;
}
__device__ __forceinline__ void split1(float v, bf16& h, bf16& l) {
    h = __float2bfloat16(v);
    l = __float2bfloat16(v - __bfloat162float(h));
}
__device__ __forceinline__ void cvt_split2(float x, float y, uint32_t& hi, uint32_t& lo) {
    __nv_bfloat162 h = __float22bfloat162_rn(make_float2(x, y));
    hi = *reinterpret_cast<uint32_t*>(&h);
    float hx = __uint_as_float(hi << 16);
    float hy = __uint_as_float(hi & 0xFFFF0000u);
    __nv_bfloat162 l = __float22bfloat162_rn(make_float2(x - hx, y - hy));
    lo = *reinterpret_cast<uint32_t*>(&l);
}
__device__ __forceinline__ void split4(float4 v, uint2& h, uint2& l) {
    cvt_split2(v.x, v.y, h.x, l.x);
    cvt_split2(v.z, v.w, h.y, l.y);
}
__device__ __forceinline__ float2 bf2f2(uint32_t u) {
    return __bfloat1622float2(*reinterpret_cast<__nv_bfloat162*>(&u));
}

#define LDSM4(r, a)                                                                        \
    asm volatile("ldmatrix.sync.aligned.m8n8.x4.shared.b16 {%0,%1,%2,%3}, [%4];"           \
                 : "=r"((r)[0]), "=r"((r)[1]), "=r"((r)[2]), "=r"((r)[3]) : "r"(a))
#define LDSM2(r, a)                                                                        \
    asm volatile("ldmatrix.sync.aligned.m8n8.x2.shared.b16 {%0,%1}, [%2];"                 \
                 : "=r"((r)[0]), "=r"((r)[1]) : "r"(a))

__device__ __forceinline__ void mma16816(float c[4], const uint32_t a[4], const uint32_t b[2]) {
    asm volatile(
        "mma.sync.aligned.m16n8k16.row.col.f32.bf16.bf16.f32 "
        "{%0,%1,%2,%3}, {%4,%5,%6,%7}, {%8,%9}, {%0,%1,%2,%3};"
        : "+f"(c[0]), "+f"(c[1]), "+f"(c[2]), "+f"(c[3])
        : "r"(a[0]), "r"(a[1]), "r"(a[2]), "r"(a[3]), "r"(b[0]), "r"(b[1]));
}

// ---------------- GEMM: C = act((A @ B'^T) * mul + bias) ----------------
// Pre-split bf16 H/L operands. Tile 128 x BN, 512 threads / 16 warps (4x4 grid),
// warp tile 32 x (BN/4), KC=32/iter. 3-term split Ah*Bh + Ah*Bl + Al*Bh, fp32 acc.
// expA: A operand holds logits; fill applies p = exp(s - rowM) * rowInvL.
// estore 4: apply mul into acc, store split logits + per-tile row max / sumexp stats.
struct GArgs {
    const bf16* AH[3]; const bf16* AL[3];
    const bf16* BH[3]; const bf16* BL[3];
    float* C[3];
    bf16* CH[3]; bf16* CL[3];
    const float* bias[3];
    const bf16* mulH; const bf16* mulL;
    const float* rowM; const float* rowInvL;
    float* Mt; float* Lt;
    int M, N, K, lda, ldb, ldc, act;
    int kLen;            // 0: bz = batch index; else bz = K-chunk index
    int expA;
    int estore[3];       // 0 fp32, 2 split, 3 split transposed, 4 split+stats
};

#define ROWB 80
#define ATILEB (128 * ROWB)

template <int BN>
__global__ void __launch_bounds__(512, 1) mma_gemm(const GArgs p) {
    constexpr int NT = BN / 32;
    constexpr int NBQ = BN / 128;
    constexpr int BTILEB = BN * ROWB;
    constexpr int STAGEB = 2 * ATILEB + 2 * BTILEB;
    extern __shared__ __align__(16) char smem[];

    const int bz = blockIdx.z;
    const int bi = p.kLen ? 0 : bz;
    const int kOff = p.kLen ? bz * p.kLen : 0;
    const int Kloc = p.kLen ? p.kLen : p.K;

    const int m0 = blockIdx.x * 128, n0 = blockIdx.y * BN;
    const int lda = p.lda, ldb = p.ldb, ldc = p.ldc;

    const bf16* __restrict__ pAH = p.AH[bi] + (size_t)m0 * lda + kOff;
    const bf16* __restrict__ pAL = p.AL[bi] + (size_t)m0 * lda + kOff;
    const bf16* __restrict__ pBH = p.BH[bi] + (size_t)n0 * ldb + kOff;
    const bf16* __restrict__ pBL = p.BL[bi] + (size_t)n0 * ldb + kOff;
    const float* __restrict__ bias = p.bias[bi];

    const int tid  = threadIdx.x;
    const int lane = tid & 31, wid = tid >> 5;
    const int wm = wid & 3, wn = wid >> 2;

    const uint32_t u0 = s2u(smem);
    const uint32_t aRowOff = (uint32_t)((lane & 15) * ROWB + ((lane & 16) ? 16 : 0));
    const uint32_t bRowOff = (uint32_t)((lane & 7) * ROWB + ((lane & 8) ? 16 : 0));

    float acc[2][NT][4];
#pragma unroll
    for (int mt = 0; mt < 2; mt++)
#pragma unroll
        for (int nt = 0; nt < NT; nt++)
#pragma unroll
            for (int q = 0; q < 4; q++) acc[mt][nt][q] = 0.f;

    uint4 rah, ral, rbh[NBQ], rbl[NBQ];
    const int fRow = tid >> 2;
    const int fC8  = (tid & 3) << 3;
    const int fOff = fRow * ROWB + ((tid & 3) << 4);

    // per-CTA-constant softmax params for expA (row of A is fixed per thread)
    float expM = 0.f, expIL = 1.f;
    if (p.expA) {
        expM = p.rowM[m0 + fRow];
        expIL = p.rowInvL[m0 + fRow];
    }

    auto loadT = [&](int k0) {
        rah = *reinterpret_cast<const uint4*>(pAH + (size_t)fRow * lda + k0 + fC8);
        ral = *reinterpret_cast<const uint4*>(pAL + (size_t)fRow * lda + k0 + fC8);
#pragma unroll
        for (int q = 0; q < NBQ; q++) {
            int row = fRow + q * 128;
            rbh[q] = *reinterpret_cast<const uint4*>(pBH + (size_t)row * ldb + k0 + fC8);
            rbl[q] = *reinterpret_cast<const uint4*>(pBL + (size_t)row * ldb + k0 + fC8);
        }
    };
    auto storeT = [&](int stage) {
        char* AHs = smem + stage * STAGEB;
        char* ALs = AHs + ATILEB;
        char* BHs = ALs + ATILEB;
        char* BLs = BHs + BTILEB;
        if (!p.expA) {
            *reinterpret_cast<uint4*>(AHs + fOff) = rah;
            *reinterpret_cast<uint4*>(ALs + fOff) = ral;
        } else {
            // reconstruct logits, apply softmax, re-split to H/L
            const uint32_t* hp = reinterpret_cast<const uint32_t*>(&rah);
            const uint32_t* lp = reinterpret_cast<const uint32_t*>(&ral);
            uint32_t oh[4], ol[4];
#pragma unroll
            for (int q = 0; q < 4; q++) {
                float2 h = bf2f2(hp[q]), l = bf2f2(lp[q]);
                float px = __expf((h.x + l.x) - expM) * expIL;
                float py = __expf((h.y + l.y) - expM) * expIL;
                cvt_split2(px, py, oh[q], ol[q]);
            }
            *reinterpret_cast<uint4*>(AHs + fOff) = make_uint4(oh[0], oh[1], oh[2], oh[3]);
            *reinterpret_cast<uint4*>(ALs + fOff) = make_uint4(ol[0], ol[1], ol[2], ol[3]);
        }
#pragma unroll
        for (int q = 0; q < NBQ; q++) {
            *reinterpret_cast<uint4*>(BHs + fOff + q * 128 * ROWB) = rbh[q];
            *reinterpret_cast<uint4*>(BLs + fOff + q * 128 * ROWB) = rbl[q];
        }
    };
    auto compute = [&](int stage) {
        const uint32_t uAH = u0 + (uint32_t)(stage * STAGEB);
        const uint32_t uAL = uAH + ATILEB;
        const uint32_t uBH = uAL + ATILEB;
        const uint32_t uBL = uBH + BTILEB;
#pragma unroll
        for (int ks = 0; ks < 2; ks++) {
            const uint32_t ka = (uint32_t)(ks * 32);
            uint32_t ah[2][4], bh[NT][2];
#pragma unroll
            for (int mt = 0; mt < 2; mt++)
                LDSM4(ah[mt], uAH + (uint32_t)((wm * 32 + mt * 16) * ROWB) + aRowOff + ka);
#pragma unroll
            for (int nt = 0; nt < NT; nt++)
                LDSM2(bh[nt], uBH + (uint32_t)((wn * (NT * 8) + nt * 8) * ROWB) + bRowOff + ka);
#pragma unroll
            for (int mt = 0; mt < 2; mt++)
#pragma unroll
                for (int nt = 0; nt < NT; nt++) mma16816(acc[mt][nt], ah[mt], bh[nt]);
#pragma unroll
            for (int nt = 0; nt < NT; nt++) {
                uint32_t bl2[2];
                LDSM2(bl2, uBL + (uint32_t)((wn * (NT * 8) + nt * 8) * ROWB) + bRowOff + ka);
#pragma unroll
                for (int mt = 0; mt < 2; mt++) mma16816(acc[mt][nt], ah[mt], bl2);
            }
#pragma unroll
            for (int mt = 0; mt < 2; mt++) {
                uint32_t alf[4];
                LDSM4(alf, uAL + (uint32_t)((wm * 32 + mt * 16) * ROWB) + aRowOff + ka);
#pragma unroll
                for (int nt = 0; nt < NT; nt++) mma16816(acc[mt][nt], alf, bh[nt]);
            }
        }
    };

    const int niter = Kloc >> 5;
    loadT(0);
    storeT(0);
    if (niter > 1) loadT(32);
    __syncthreads();
    for (int i = 0; i < niter; i++) {
        if (i + 1 < niter) storeT((i + 1) & 1);
        if (i + 2 < niter) loadT((i + 2) << 5);
        compute(i & 1);
        __syncthreads();
    }

    // ---------------- epilogue ----------------
    const int es = p.estore[bz];
    float* __restrict__ C  = p.C[bz];
    bf16* __restrict__ CH = p.CH[bz];
    bf16* __restrict__ CL = p.CL[bz];

    if (es == 4) {
        // acc <- mul * acc ; per-row max & sumexp stats; split logits store
        const bf16* __restrict__ mulH = p.mulH;
        const bf16* __restrict__ mulL = p.mulL;
        float* spart = reinterpret_cast<float*>(smem);            // [128][16]
        float* srow  = spart + 128 * 16;                          // [128]
        const int scol = wn * 4 + (lane & 3);
        float lmax[2][2] = {{-3.4e38f, -3.4e38f}, {-3.4e38f, -3.4e38f}};
#pragma unroll
        for (int mt = 0; mt < 2; mt++)
#pragma unroll
            for (int nt = 0; nt < NT; nt++) {
                int mA = m0 + wm * 32 + mt * 16 + (lane >> 2);
                int n  = n0 + wn * (NT * 8) + nt * 8 + 2 * (lane & 3);
#pragma unroll
                for (int h = 0; h < 2; h++) {
                    int mm = mA + h * 8;
                    float2 mh = bf2f2(*reinterpret_cast<const uint32_t*>(&mulH[(size_t)mm * ldc + n]));
                    float2 ml = bf2f2(*reinterpret_cast<const uint32_t*>(&mulL[(size_t)mm * ldc + n]));
                    acc[mt][nt][2 * h + 0] *= (mh.x + ml.x);
                    acc[mt][nt][2 * h + 1] *= (mh.y + ml.y);
                    lmax[mt][h] = fmaxf(lmax[mt][h],
                                        fmaxf(acc[mt][nt][2 * h + 0], acc[mt][nt][2 * h + 1]));
                }
            }
#pragma unroll
        for (int mt = 0; mt < 2; mt++)
#pragma unroll
            for (int h = 0; h < 2; h++) {
                int rowl = wm * 32 + mt * 16 + h * 8 + (lane >> 2);
                spart[rowl * 16 + scol] = lmax[mt][h];
            }
        __syncthreads();
        if (tid < 128) {
            float m = spart[tid * 16];
#pragma unroll
            for (int k = 1; k < 16; k++) m = fmaxf(m, spart[tid * 16 + k]);
            srow[tid] = m;
        }
        __syncthreads();
        float lsum[2][2] = {{0.f, 0.f}, {0.f, 0.f}};
#pragma unroll
        for (int mt = 0; mt < 2; mt++)
#pragma unroll
            for (int h = 0; h < 2; h++) {
                int rowl = wm * 32 + mt * 16 + h * 8 + (lane >> 2);
                float m = srow[rowl];
#pragma unroll
                for (int nt = 0; nt < NT; nt++) {
                    lsum[mt][h] += __expf(acc[mt][nt][2 * h + 0] - m);
                    lsum[mt][h] += __expf(acc[mt][nt][2 * h + 1] - m);
                }
            }
        __syncthreads();
#pragma unroll
        for (int mt = 0; mt < 2; mt++)
#pragma unroll
            for (int h = 0; h < 2; h++) {
                int rowl = wm * 32 + mt * 16 + h * 8 + (lane >> 2);
                spart[rowl * 16 + scol] = lsum[mt][h];
            }
        __syncthreads();
        if (tid < 128) {
            float L = 0.f;
#pragma unroll
            for (int k = 0; k < 16; k++) L += spart[tid * 16 + k];
            p.Mt[(size_t)blockIdx.y * p.M + m0 + tid] = srow[tid];
            p.Lt[(size_t)blockIdx.y * p.M + m0 + tid] = L;
        }
        // split logit stores
#pragma unroll
        for (int mt = 0; mt < 2; mt++)
#pragma unroll
            for (int nt = 0; nt < NT; nt++) {
                int mA = m0 + wm * 32 + mt * 16 + (lane >> 2);
                int n  = n0 + wn * (NT * 8) + nt * 8 + 2 * (lane & 3);
#pragma unroll
                for (int h = 0; h < 2; h++) {
                    int mm = mA + h * 8;
                    uint32_t hi, lo;
                    cvt_split2(acc[mt][nt][2 * h + 0], acc[mt][nt][2 * h + 1], hi, lo);
                    *reinterpret_cast<uint32_t*>(&CH[(size_t)mm * ldc + n]) = hi;
                    *reinterpret_cast<uint32_t*>(&CL[(size_t)mm * ldc + n]) = lo;
                }
            }
        return;
    }

    if (es == 3) {
        bf16* sH = reinterpret_cast<bf16*>(smem);
        bf16* sL = reinterpret_cast<bf16*>(smem + BN * 128 * 2);
#pragma unroll
        for (int mt = 0; mt < 2; mt++)
#pragma unroll
            for (int nt = 0; nt < NT; nt++) {
                int ml = wm * 32 + mt * 16 + (lane >> 2);
                int nl = wn * (NT * 8) + nt * 8 + 2 * (lane & 3);
#pragma unroll
                for (int h = 0; h < 2; h++) {
                    int mm = ml + h * 8;
                    float vx = acc[mt][nt][2 * h + 0];
                    float vy = acc[mt][nt][2 * h + 1];
                    if (bias) { vx += bias[n0 + nl]; vy += bias[n0 + nl + 1]; }
                    if (p.act) { vx = fmaxf(vx, 0.f); vy = fmaxf(vy, 0.f); }
                    bf16 hx, lx, hy, ly;
                    split1(vx, hx, lx);
                    split1(vy, hy, ly);
                    sH[nl * 128 + mm] = hx;       sL[nl * 128 + mm] = lx;
                    sH[(nl + 1) * 128 + mm] = hy; sL[(nl + 1) * 128 + mm] = ly;
                }
            }
        __syncthreads();
        const int nchunks = BN * 128 / 8;
        for (int idx = tid; idx < nchunks; idx += 512) {
            int nrow = idx >> 4;
            int seg  = (idx & 15) * 8;
            *reinterpret_cast<uint4*>(&CH[(size_t)(n0 + nrow) * p.M + m0 + seg]) =
                *reinterpret_cast<uint4*>(&sH[nrow * 128 + seg]);
            *reinterpret_cast<uint4*>(&CL[(size_t)(n0 + nrow) * p.M + m0 + seg]) =
                *reinterpret_cast<uint4*>(&sL[nrow * 128 + seg]);
        }
        return;
    }

#pragma unroll
    for (int mt = 0; mt < 2; mt++) {
#pragma unroll
        for (int nt = 0; nt < NT; nt++) {
            int mA = m0 + wm * 32 + mt * 16 + (lane >> 2);
            int n  = n0 + wn * (NT * 8) + nt * 8 + 2 * (lane & 3);
#pragma unroll
            for (int h = 0; h < 2; h++) {
                int mm = mA + h * 8;
                float vx = acc[mt][nt][2 * h + 0];
                float vy = acc[mt][nt][2 * h + 1];
                if (bias) { vx += bias[n]; vy += bias[n + 1]; }
                if (p.act) { vx = fmaxf(vx, 0.f); vy = fmaxf(vy, 0.f); }
                if (es == 0) {
                    *reinterpret_cast<float2*>(&C[(size_t)mm * ldc + n]) = make_float2(vx, vy);
                } else {  // es == 2
                    uint32_t hi, lo;
                    cvt_split2(vx, vy, hi, lo);
                    *reinterpret_cast<uint32_t*>(&CH[(size_t)mm * ldc + n]) = hi;
                    *reinterpret_cast<uint32_t*>(&CL[(size_t)mm * ldc + n]) = lo;
                }
            }
        }
    }
}

// ---- combine per-tile stats -> row max + 1/L ----
__global__ void combine_ml_k() {
    int r = blockIdx.x * 256 + threadIdx.x;
    if (r >= NND) return;
    float m = -3.4e38f;
#pragma unroll 4
    for (int t = 0; t < NTILES; t++) m = fmaxf(m, g_Mt[t * NND + r]);
    float L = 0.f;
#pragma unroll 4
    for (int t = 0; t < NTILES; t++) L += g_Lt[t * NND + r] * __expf(g_Mt[t * NND + r] - m);
    g_rowM[r] = m;
    g_rowInvL[r] = 1.f / L;
}

// ---- split-K reduce: x = relu(sum part + bias) -> bf16 H/L ----
__global__ void reduce_split_k(const float* __restrict__ bias, bf16* __restrict__ oH,
                               bf16* __restrict__ oL) {
    const int n4 = NND * NHID / 4;
    const size_t S = (size_t)NND * NHID;
    for (int e = blockIdx.x * blockDim.x + threadIdx.x; e < n4; e += gridDim.x * blockDim.x) {
        float4 a = reinterpret_cast<const float4*>(g_part)[e];
        float4 b = reinterpret_cast<const float4*>(g_part + S)[e];
        float4 c = reinterpret_cast<const float4*>(g_part + 2 * S)[e];
        int col = (e * 4) & (NHID - 1);
        float4 v;
        v.x = fmaxf(a.x + b.x + c.x + bias[col + 0], 0.f);
        v.y = fmaxf(a.y + b.y + c.y + bias[col + 1], 0.f);
        v.z = fmaxf(a.z + b.z + c.z + bias[col + 2], 0.f);
        v.w = fmaxf(a.w + b.w + c.w + bias[col + 3], 0.f);
        uint2 h, l;
        split4(v, h, l);
        reinterpret_cast<uint2*>(oH)[e] = h;
        reinterpret_cast<uint2*>(oL)[e] = l;
    }
}

// ---- fused: xt = relu(sum part); xtw2 = xt @ W2  (one warp per row) ----
__global__ void reduce_xtw2_k(const float* __restrict__ W2) {
    int row  = blockIdx.x * 8 + (threadIdx.x >> 5);
    int lane = threadIdx.x & 31;
    if (row >= NND) return;
    const size_t S = (size_t)NND * NHID;
    const float* p0 = g_part + (size_t)row * NHID;
    float acc[8] = {0, 0, 0, 0, 0, 0, 0, 0};
    for (int h = lane; h < NHID; h += 32) {
        float xv = fmaxf(p0[h] + p0[S + h] + p0[2 * S + h], 0.f);
        const float4* wp = reinterpret_cast<const float4*>(&W2[h * 8]);
        float4 wlo = wp[0], whi = wp[1];
        acc[0] = fmaf(xv, wlo.x, acc[0]);
        acc[1] = fmaf(xv, wlo.y, acc[1]);
        acc[2] = fmaf(xv, wlo.z, acc[2]);
        acc[3] = fmaf(xv, wlo.w, acc[3]);
        acc[4] = fmaf(xv, whi.x, acc[4]);
        acc[5] = fmaf(xv, whi.y, acc[5]);
        acc[6] = fmaf(xv, whi.z, acc[6]);
        acc[7] = fmaf(xv, whi.w, acc[7]);
    }
#pragma unroll
    for (int c = 0; c < 8; c++)
#pragma unroll
        for (int off = 16; off; off >>= 1) acc[c] += __shfl_down_sync(0xffffffffu, acc[c], off);
    if (lane == 0) {
#pragma unroll
        for (int c = 0; c < 8; c++) g_xtw2[row * 8 + c] = acc[c];
    }
}

// ---------------- transpose + split ----------------
struct TSArgs {
    const float* in[3];
    bf16* oH[3]; bf16* oL[3];
    int R, C;
};
__global__ void transpose_split_k(const TSArgs p) {
    __shared__ float t[32][33];
    const float* __restrict__ in = p.in[blockIdx.z];
    bf16* __restrict__ oH = p.oH[blockIdx.z];
    bf16* __restrict__ oL = p.oL[blockIdx.z];
    const int R = p.R, C = p.C;
    int c0 = blockIdx.x * 32, r0 = blockIdx.y * 32;
    int x = threadIdx.x, y = threadIdx.y;
#pragma unroll
    for (int i = 0; i < 32; i += 8) t[y + i][x] = in[(size_t)(r0 + y + i) * C + c0 + x];
    __syncthreads();
#pragma unroll
    for (int i = 0; i < 32; i += 8) {
        float v = t[x][y + i];
        bf16 h, l;
        split1(v, h, l);
        oH[(size_t)(c0 + y + i) * R + r0 + x] = h;
        oL[(size_t)(c0 + y + i) * R + r0 + x] = l;
    }
}

// ---------------- elementwise split ----------------
__global__ void split_k(const float* __restrict__ in, bf16* __restrict__ oH,
                        bf16* __restrict__ oL, int n4) {
    for (int e = blockIdx.x * blockDim.x + threadIdx.x; e < n4; e += gridDim.x * blockDim.x) {
        float4 v = reinterpret_cast<const float4*>(in)[e];
        uint2 h, l;
        split4(v, h, l);
        reinterpret_cast<uint2*>(oH)[e] = h;
        reinterpret_cast<uint2*>(oL)[e] = l;
    }
}

// ---- fold: Wfold[l][j][c] = sum_k Wa_l[j,k] * Wagg[l*128+k, c]; bfold = ba@Wagg+bagg
__global__ void fold_k(const float* __restrict__ Wa1, const float* __restrict__ Wa2,
                       const float* __restrict__ Wa3, const float* __restrict__ Wagg,
                       const float* __restrict__ bagg, const float* __restrict__ ba1,
                       const float* __restrict__ ba2, const float* __restrict__ ba3) {
    int j = blockIdx.x * 128 + threadIdx.x;
    int l = blockIdx.y;
    const float* Wa = (l == 0) ? Wa1 : (l == 1) ? Wa2 : Wa3;
    float c0 = 0.f, c1 = 0.f, c2 = 0.f;
    for (int k = 0; k < ADIM; k++) {
        float a = Wa[(size_t)j * ADIM + k];
        const float* wg = &Wagg[(l * ADIM + k) * 3];
        c0 = fmaf(a, wg[0], c0);
        c1 = fmaf(a, wg[1], c1);
        c2 = fmaf(a, wg[2], c2);
    }
    g_wfold[(l * 3 + 0) * NND + j] = c0;
    g_wfold[(l * 3 + 1) * NND + j] = c1;
    g_wfold[(l * 3 + 2) * NND + j] = c2;
    if (blockIdx.x == 0 && l == 0 && threadIdx.x < 3) {
        int c = threadIdx.x;
        float b = bagg[c];
        for (int k = 0; k < ADIM; k++) {
            b += ba1[k] * Wagg[k * 3 + c];
            b += ba2[k] * Wagg[(ADIM + k) * 3 + c];
            b += ba3[k] * Wagg[(2 * ADIM + k) * 3 + c];
        }
        g_bfold[c] = b;
    }
}

// ---- gemv+gate ----
#define GV_ROWS 32
#define GV_CH 512
__device__ __forceinline__ float dot4(float4 a, float4 b) {
    return a.x * b.x + a.y * b.y + a.z * b.z + a.w * b.w;
}
__global__ void gemv_nz_k(const float* __restrict__ a0, const float* __restrict__ a1,
                          const float* __restrict__ a2, float* __restrict__ out_nz,
                          int write_out) {
    __shared__ float sw[9][GV_CH];
    const int tid = threadIdx.x;
    const int lane = tid & 31, warp = tid >> 5;
    const int rbase = blockIdx.x * GV_ROWS + warp * 4;
    float s[4][3];
#pragma unroll
    for (int r = 0; r < 4; r++)
#pragma unroll
        for (int c = 0; c < 3; c++) s[r][c] = 0.f;

    for (int ch = 0; ch < NND; ch += GV_CH) {
        __syncthreads();
        for (int idx = tid; idx < 9 * GV_CH; idx += 256) {
            int t = idx / GV_CH, j = idx % GV_CH;
            sw[t][j] = g_wfold[(size_t)t * NND + ch + j];
        }
        __syncthreads();
#pragma unroll 2
        for (int j = lane * 4; j < GV_CH; j += 128) {
            float4 wv[9];
#pragma unroll
            for (int t = 0; t < 9; t++) wv[t] = *reinterpret_cast<const float4*>(&sw[t][j]);
#pragma unroll
            for (int r = 0; r < 4; r++) {
                size_t off = (size_t)(rbase + r) * NND + ch + j;
                float4 v0 = *reinterpret_cast<const float4*>(a0 + off);
                float4 v1 = *reinterpret_cast<const float4*>(a1 + off);
                float4 v2 = *reinterpret_cast<const float4*>(a2 + off);
                s[r][0] += dot4(v0, wv[0]) + dot4(v1, wv[3]) + dot4(v2, wv[6]);
                s[r][1] += dot4(v0, wv[1]) + dot4(v1, wv[4]) + dot4(v2, wv[7]);
                s[r][2] += dot4(v0, wv[2]) + dot4(v1, wv[5]) + dot4(v2, wv[8]);
            }
        }
    }
#pragma unroll
    for (int r = 0; r < 4; r++)
#pragma unroll
        for (int c = 0; c < 3; c++) {
            float v = s[r][c];
#pragma unroll
            for (int off = 16; off; off >>= 1) v += __shfl_down_sync(0xffffffffu, v, off);
            s[r][c] = v;
        }
    if (lane == 0) {
#pragma unroll
        for (int r = 0; r < 4; r++) {
            int row = rbase + r;
            float z0 = s[r][0] + g_bfold[0];
            float z1 = s[r][1] + g_bfold[1];
            float z2 = s[r][2] + g_bfold[2];
            float mx = fmaxf(z0, fmaxf(z1, z2));
            float e0 = expf(z0 - mx), e1 = expf(z1 - mx), e2 = expf(z2 - mx);
            float inv = 1.f / (e0 + e1 + e2);
            e0 *= inv; e1 *= inv; e2 *= inv;
            g_nzT[0 * NND + row] = e0;
            g_nzT[1 * NND + row] = e1;
            g_nzT[2 * NND + row] = e2;
            if (write_out) {
                out_nz[row * 3 + 0] = e0;
                out_nz[row * 3 + 1] = e1;
                out_nz[row * 3 + 2] = e2;
            }
        }
    }
}

// ---- adj = col-weighted mix; emit bf16 H/L ----
__global__ void build_adj_k(const float* __restrict__ a0, const float* __restrict__ a1,
                            const float* __restrict__ a2) {
    const size_t total8 = (size_t)NND * NND / 8;
    for (size_t e = (size_t)blockIdx.x * blockDim.x + threadIdx.x; e < total8;
         e += (size_t)gridDim.x * blockDim.x) {
        size_t off = e * 8;
        int j = (int)(off % NND);
#pragma unroll
        for (int u = 0; u < 2; u++) {
            size_t o = off + u * 4;
            int jj = j + u * 4;
            float4 w0 = *reinterpret_cast<const float4*>(&g_nzT[jj]);
            float4 w1 = *reinterpret_cast<const float4*>(&g_nzT[NND + jj]);
            float4 w2 = *reinterpret_cast<const float4*>(&g_nzT[2 * NND + jj]);
            float4 x0 = *reinterpret_cast<const float4*>(a0 + o);
            float4 x1 = *reinterpret_cast<const float4*>(a1 + o);
            float4 x2 = *reinterpret_cast<const float4*>(a2 + o);
            float4 r;
            r.x = w0.x * x0.x + w1.x * x1.x + w2.x * x2.x;
            r.y = w0.y * x0.y + w1.y * x1.y + w2.y * x2.y;
            r.z = w0.z * x0.z + w1.z * x1.z + w2.z * x2.z;
            r.w = w0.w * x0.w + w1.w * x1.w + w2.w * x2.w;
            uint2 h, l;
            split4(r, h, l);
            *reinterpret_cast<uint2*>(&g_adjH[o]) = h;
            *reinterpret_cast<uint2*>(&g_adjL[o]) = l;
        }
    }
}

// ---------------- z = (adjH+adjL) @ xtw2 + b2 ; out = softmax(z). 8 rows/CTA ----
__global__ void final_k(const float* __restrict__ b2, float* __restrict__ out) {
    const int r0  = blockIdx.x * 8;
    const int tid = threadIdx.x;
    float acc[8][8];
#pragma unroll
    for (int r = 0; r < 8; r++)
#pragma unroll
        for (int c = 0; c < 8; c++) acc[r][c] = 0.f;

    for (int j4 = tid; j4 < NND / 4; j4 += 256) {
        float4 w[8];
        const float4* wp = reinterpret_cast<const float4*>(&g_xtw2[(size_t)j4 * 32]);
#pragma unroll
        for (int q = 0; q < 8; q++) w[q] = wp[q];
#pragma unroll
        for (int r = 0; r < 8; r++) {
            size_t off = (size_t)(r0 + r) * NND + j4 * 4;
            uint2 hz = *reinterpret_cast<const uint2*>(&g_adjH[off]);
            uint2 lz = *reinterpret_cast<const uint2*>(&g_adjL[off]);
            float2 h0 = bf2f2(hz.x), h1 = bf2f2(hz.y);
            float2 l0 = bf2f2(lz.x), l1 = bf2f2(lz.y);
            float av[4] = {h0.x + l0.x, h0.y + l0.y, h1.x + l1.x, h1.y + l1.y};
#pragma unroll
            for (int q = 0; q < 4; q++) {
                acc[r][0] = fmaf(av[q], w[2 * q].x, acc[r][0]);
                acc[r][1] = fmaf(av[q], w[2 * q].y, acc[r][1]);
                acc[r][2] = fmaf(av[q], w[2 * q].z, acc[r][2]);
                acc[r][3] = fmaf(av[q], w[2 * q].w, acc[r][3]);
                acc[r][4] = fmaf(av[q], w[2 * q + 1].x, acc[r][4]);
                acc[r][5] = fmaf(av[q], w[2 * q + 1].y, acc[r][5]);
                acc[r][6] = fmaf(av[q], w[2 * q + 1].z, acc[r][6]);
                acc[r][7] = fmaf(av[q], w[2 * q + 1].w, acc[r][7]);
            }
        }
    }

    __shared__ float sred[8][64];
    const int lane = tid & 31, warp = tid >> 5;
#pragma unroll
    for (int r = 0; r < 8; r++)
#pragma unroll
        for (int c = 0; c < 8; c++) {
            float vv = acc[r][c];
#pragma unroll
            for (int off = 16; off; off >>= 1) vv += __shfl_down_sync(0xffffffffu, vv, off);
            if (lane == 0) sred[warp][r * 8 + c] = vv;
        }
    __syncthreads();
    if (tid < 64) {
        float v = 0.f;
#pragma unroll
        for (int w = 0; w < 8; w++) v += sred[w][tid];
        int c = tid & 7;
        v += b2[c];
        float mx = v;
#pragma unroll
        for (int off = 4; off; off >>= 1) mx = fmaxf(mx, __shfl_xor_sync(0xffffffffu, mx, off, 8));
        float e = expf(v - mx);
        float s = e;
#pragma unroll
        for (int off = 4; off; off >>= 1) s += __shfl_xor_sync(0xffffffffu, s, off, 8);
        out[(size_t)(r0 + (tid >> 3)) * 8 + c] = e / s;
    }
}

// ---------------- host side ----------------
template <typename T>
static T* symaddr(const void* sym) {
    void* p = nullptr;
    cudaGetSymbolAddress(&p, sym);
    return (T*)p;
}

#define GSMEM128 (2 * (2 * ATILEB + 2 * 128 * ROWB))   // 81920
#define GSMEM256 (2 * (2 * ATILEB + 2 * 256 * ROWB))   // 122880

extern "C" void kernel_launch(void* const* d_in, const int* in_sizes, int n_in,
                              void* d_out, int out_size) {
    const float* adj0 = (const float*)d_in[0];
    const float* adj1 = (const float*)d_in[1];
    const float* adj2 = (const float*)d_in[2];
    const float* feats = (const float*)d_in[3];
    const float* Wa1 = (const float*)d_in[4];
    const float* ba1 = (const float*)d_in[5];
    const float* Wa2 = (const float*)d_in[6];
    const float* ba2 = (const float*)d_in[7];
    const float* Wa3 = (const float*)d_in[8];
    const float* ba3 = (const float*)d_in[9];
    const float* Wagg = (const float*)d_in[10];
    const float* bagg = (const float*)d_in[11];
    const float* W1 = (const float*)d_in[12];
    const float* b1 = (const float*)d_in[13];
    const float* Wq = (const float*)d_in[14];
    const float* bq = (const float*)d_in[15];
    const float* Wk = (const float*)d_in[16];
    const float* bk = (const float*)d_in[17];
    const float* Wv = (const float*)d_in[18];
    const float* bv = (const float*)d_in[19];
    const float* W2 = (const float*)d_in[20];
    const float* b2 = (const float*)d_in[21];
    float* out = (float*)d_out;

    float* partp = symaddr<float>(g_part);
    float* Mtp   = symaddr<float>(g_Mt);
    float* Ltp   = symaddr<float>(g_Lt);
    float* rowMp = symaddr<float>(g_rowM);
    float* rowIp = symaddr<float>(g_rowInvL);
    bf16* adjH = symaddr<bf16>(g_adjH);   bf16* adjL = symaddr<bf16>(g_adjL);
    bf16* attH = symaddr<bf16>(g_attH);   bf16* attL = symaddr<bf16>(g_attL);
    bf16* ftH  = symaddr<bf16>(g_featsH); bf16* ftL  = symaddr<bf16>(g_featsL);
    bf16* W1TH = symaddr<bf16>(g_W1TH);   bf16* W1TL = symaddr<bf16>(g_W1TL);
    bf16* WqTH = symaddr<bf16>(g_WqTH);   bf16* WqTL = symaddr<bf16>(g_WqTL);
    bf16* WkTH = symaddr<bf16>(g_WkTH);   bf16* WkTL = symaddr<bf16>(g_WkTL);
    bf16* WvTH = symaddr<bf16>(g_WvTH);   bf16* WvTL = symaddr<bf16>(g_WvTL);
    bf16* fW1TH = symaddr<bf16>(g_fW1TH); bf16* fW1TL = symaddr<bf16>(g_fW1TL);
    bf16* xH   = symaddr<bf16>(g_xH);     bf16* xL   = symaddr<bf16>(g_xL);
    bf16* QH   = symaddr<bf16>(g_QH);     bf16* QL   = symaddr<bf16>(g_QL);
    bf16* KHp  = symaddr<bf16>(g_KHb);    bf16* KLp  = symaddr<bf16>(g_KLb);
    bf16* VTH  = symaddr<bf16>(g_VTH);    bf16* VTL  = symaddr<bf16>(g_VTL);

    cudaFuncSetAttribute(mma_gemm<128>, cudaFuncAttributeMaxDynamicSharedMemorySize, GSMEM128);
    cudaFuncSetAttribute(mma_gemm<256>, cudaFuncAttributeMaxDynamicSharedMemorySize, GSMEM256);

    int write_nz = (out_size >= NND * (NCLASS + 3)) ? 1 : 0;
    const size_t PS = (size_t)NND * NHID;

    // 0: feats split
    split_k<<<592, 256>>>(feats, ftH, ftL, NND * NFEAT / 4);
    // 1: W1 transpose+split
    {
        TSArgs t{};
        t.in[0] = W1; t.oH[0] = W1TH; t.oL[0] = W1TL; t.R = NFEAT; t.C = NHID;
        transpose_split_k<<<dim3(NHID / 32, NFEAT / 32, 1), dim3(32, 8)>>>(t);
    }
    // 2: fold
    fold_k<<<dim3(NND / 128, 3), 128>>>(Wa1, Wa2, Wa3, Wagg, bagg, ba1, ba2, ba3);

    // 3: L4: fW1^T(split) = (feats @ W1)^T
    {
        GArgs a{};
        a.AH[0] = ftH; a.AL[0] = ftL;
        a.BH[0] = W1TH; a.BL[0] = W1TL;
        a.CH[0] = fW1TH; a.CL[0] = fW1TL;
        a.M = NND; a.N = NHID; a.K = NFEAT; a.lda = NFEAT; a.ldb = NFEAT; a.ldc = NHID;
        a.estore[0] = 3;
        mma_gemm<128><<<dim3(48, 2, 1), 512, GSMEM128>>>(a);
    }

    // 4: gemv + gate softmax -> nz
    gemv_nz_k<<<NND / GV_ROWS, 256>>>(adj0, adj1, adj2, out + (size_t)NND * NCLASS, write_nz);
    // 5: Wq/Wk/Wv transpose+split (batched)
    {
        TSArgs t{};
        t.in[0] = Wq; t.in[1] = Wk; t.in[2] = Wv;
        t.oH[0] = WqTH; t.oH[1] = WkTH; t.oH[2] = WvTH;
        t.oL[0] = WqTL; t.oL[1] = WkTL; t.oL[2] = WvTL;
        t.R = NHID; t.C = NHID;
        transpose_split_k<<<dim3(NHID / 32, NHID / 32, 3), dim3(32, 8)>>>(t);
    }
    // 6: fused adjacency (bf16 H/L)
    build_adj_k<<<1184, 256>>>(adj0, adj1, adj2);

    // 7: L5 split-K (BN=256)
    {
        GArgs a{};
        a.AH[0] = adjH; a.AL[0] = adjL;
        a.BH[0] = fW1TH; a.BL[0] = fW1TL;
        a.C[0] = partp; a.C[1] = partp + PS; a.C[2] = partp + 2 * PS;
        a.M = NND; a.N = NHID; a.K = NND; a.lda = NND; a.ldb = NND; a.ldc = NHID;
        a.kLen = NND / 3;
        a.estore[0] = a.estore[1] = a.estore[2] = 0;
        mma_gemm<256><<<dim3(48, 1, 3), 512, GSMEM256>>>(a);
    }
    // 8: reduce -> x (split)
    reduce_split_k<<<1536, 256>>>(b1, xH, xL);

    // 9: L6: Q,K (split); V (split transposed, staged)
    {
        GArgs a{};
        a.AH[0] = a.AH[1] = a.AH[2] = xH;
        a.AL[0] = a.AL[1] = a.AL[2] = xL;
        a.BH[0] = WqTH; a.BH[1] = WkTH; a.BH[2] = WvTH;
        a.BL[0] = WqTL; a.BL[1] = WkTL; a.BL[2] = WvTL;
        a.CH[0] = QH; a.CL[0] = QL;
        a.CH[1] = KHp; a.CL[1] = KLp;
        a.CH[2] = VTH; a.CL[2] = VTL;
        a.bias[0] = bq; a.bias[1] = bk; a.bias[2] = bv;
        a.M = NND; a.N = NHID; a.K = NHID; a.lda = NHID; a.ldb = NHID; a.ldc = NHID;
        a.estore[0] = 2; a.estore[1] = 2; a.estore[2] = 3;
        mma_gemm<128><<<dim3(48, 2, 3), 512, GSMEM128>>>(a);
    }

    // 10: L7': masked logits (split store) + per-tile row max/sumexp stats
    {
        GArgs a{};
        a.AH[0] = QH; a.AL[0] = QL;
        a.BH[0] = KHp; a.BL[0] = KLp;
        a.CH[0] = attH; a.CL[0] = attL;
        a.mulH = adjH; a.mulL = adjL;
        a.Mt = Mtp; a.Lt = Ltp;
        a.M = NND; a.N = NND; a.K = NHID; a.lda = NHID; a.ldb = NHID; a.ldc = NND;
        a.estore[0] = 4;
        mma_gemm<128><<<dim3(48, 48, 1), 512, GSMEM128>>>(a);
    }

    // 11: combine tile stats -> row M, 1/L
    combine_ml_k<<<NND / 256, 256>>>();

    // 12: L9' split-K (BN=256), softmax applied in A-fill
    {
        GArgs a{};
        a.AH[0] = attH; a.AL[0] = attL;
        a.BH[0] = VTH; a.BL[0] = VTL;
        a.C[0] = partp; a.C[1] = partp + PS; a.C[2] = partp + 2 * PS;
        a.rowM = rowMp; a.rowInvL = rowIp;
        a.expA = 1;
        a.M = NND; a.N = NHID; a.K = NND; a.lda = NND; a.ldb = NND; a.ldc = NHID;
        a.kLen = NND / 3;
        a.estore[0] = a.estore[1] = a.estore[2] = 0;
        mma_gemm<256><<<dim3(48, 1, 3), 512, GSMEM256>>>(a);
    }

    // 13: fused reduce(relu) + @W2
    reduce_xtw2_k<<<768, 256>>>(W2);
    // 14: final
    final_k<<<768, 256>>>(b2, out);
}

// round 13
// speedup vs baseline: 1.1064x; 1.1064x over previous
#include <cuda_runtime.h>
#include <cuda_bf16.h>
#include <math.h>
#include <stdint.h>

#define NND    6144
#define NFEAT  512
#define NHID   256
#define NCLASS 8
#define ADIM   128

typedef __nv_bfloat16 bf16;

// ---------------- device scratch (no allocations allowed) ----------------
__device__ float g_nzT[3 * NND];
__device__ float g_wfold[3 * NND * 4];
__device__ float g_bfold[3];
__device__ float g_att[(size_t)NND * NND];
__device__ float g_part[3 * (size_t)NND * NHID];
__device__ float g_xtw2[NND * NCLASS];

__device__ bf16 g_adjH[(size_t)NND * NND],   g_adjL[(size_t)NND * NND];
__device__ bf16 g_attH[(size_t)NND * NND],   g_attL[(size_t)NND * NND];
__device__ bf16 g_featsH[(size_t)NND * NFEAT], g_featsL[(size_t)NND * NFEAT];
__device__ bf16 g_W1TH[NHID * NFEAT],  g_W1TL[NHID * NFEAT];
__device__ bf16 g_WqTH[NHID * NHID],   g_WqTL[NHID * NHID];
__device__ bf16 g_WkTH[NHID * NHID],   g_WkTL[NHID * NHID];
__device__ bf16 g_WvTH[NHID * NHID],   g_WvTL[NHID * NHID];
__device__ bf16 g_fW1TH[(size_t)NHID * NND], g_fW1TL[(size_t)NHID * NND];
__device__ bf16 g_xH[(size_t)NND * NHID],  g_xL[(size_t)NND * NHID];
__device__ bf16 g_QH[(size_t)NND * NHID],  g_QL[(size_t)NND * NHID];
__device__ bf16 g_KHb[(size_t)NND * NHID], g_KLb[(size_t)NND * NHID];
__device__ bf16 g_VTH[(size_t)NHID * NND], g_VTL[(size_t)NHID * NND];

// ---------------- helpers ----------------
__device__ __forceinline__ uint32_t s2u(const void* p) {
    uint32_t a;
    asm("{ .reg .u64 t; cvta.to.shared.u64 t, %1; cvt.u32.u64 %0, t; }" : "=r"(a) : "l"(p));
    return a;
}
__device__ __forceinline__ void split1(float v, bf16& h, bf16& l) {
    h = __float2bfloat16(v);
    l = __float2bfloat16(v - __bfloat162float(h));
}
__device__ __forceinline__ void cvt_split2(float x, float y, uint32_t& hi, uint32_t& lo) {
    __nv_bfloat162 h = __float22bfloat162_rn(make_float2(x, y));
    hi = *reinterpret_cast<uint32_t*>(&h);
    float hx = __uint_as_float(hi << 16);
    float hy = __uint_as_float(hi & 0xFFFF0000u);
    __nv_bfloat162 l = __float22bfloat162_rn(make_float2(x - hx, y - hy));
    lo = *reinterpret_cast<uint32_t*>(&l);
}
__device__ __forceinline__ void split4(float4 v, uint2& h, uint2& l) {
    cvt_split2(v.x, v.y, h.x, l.x);
    cvt_split2(v.z, v.w, h.y, l.y);
}
__device__ __forceinline__ float2 bf2f2(uint32_t u) {
    return __bfloat1622float2(*reinterpret_cast<__nv_bfloat162*>(&u));
}

#define LDSM4(r, a)                                                                        \
    asm volatile("ldmatrix.sync.aligned.m8n8.x4.shared.b16 {%0,%1,%2,%3}, [%4];"           \
                 : "=r"((r)[0]), "=r"((r)[1]), "=r"((r)[2]), "=r"((r)[3]) : "r"(a))
#define LDSM2(r, a)                                                                        \
    asm volatile("ldmatrix.sync.aligned.m8n8.x2.shared.b16 {%0,%1}, [%2];"                 \
                 : "=r"((r)[0]), "=r"((r)[1]) : "r"(a))

__device__ __forceinline__ void mma16816(float c[4], const uint32_t a[4], const uint32_t b[2]) {
    asm volatile(
        "mma.sync.aligned.m16n8k16.row.col.f32.bf16.bf16.f32 "
        "{%0,%1,%2,%3}, {%4,%5,%6,%7}, {%8,%9}, {%0,%1,%2,%3};"
        : "+f"(c[0]), "+f"(c[1]), "+f"(c[2]), "+f"(c[3])
        : "r"(a[0]), "r"(a[1]), "r"(a[2]), "r"(a[3]), "r"(b[0]), "r"(b[1]));
}

// ---------------- GEMM: C = act((A @ B'^T) * mul + bias) ----------------
// Pre-split bf16 H/L operands. Tile 128 x BN, 512 threads / 16 warps (4x4 grid),
// warp tile 32 x (BN/4), KC=32/iter. 3-term split Ah*Bh + Ah*Bl + Al*Bh, fp32 acc.
struct GArgs {
    const bf16* AH[3]; const bf16* AL[3];
    const bf16* BH[3]; const bf16* BL[3];
    float* C[3];
    bf16* CH[3]; bf16* CL[3];
    const float* bias[3];
    const bf16* mulH; const bf16* mulL;   // optional elementwise mul (reconstruct H+L)
    int M, N, K, lda, ldb, ldc, act;
    int kLen;            // 0: bz = batch index; else bz = K-chunk index
    int estore[3];       // 0 fp32, 2 split, 3 split transposed (BN==128 only)
};

#define ROWB 80
#define ATILEB (128 * ROWB)

template <int BN>
__global__ void __launch_bounds__(512, 1) mma_gemm(const GArgs p) {
    constexpr int NT = BN / 32;              // n-tiles per warp
    constexpr int NBQ = BN / 128;            // B fill chunks per thread per tile
    constexpr int BTILEB = BN * ROWB;
    constexpr int STAGEB = 2 * ATILEB + 2 * BTILEB;
    extern __shared__ __align__(16) char smem[];

    const int bz = blockIdx.z;
    const int bi = p.kLen ? 0 : bz;
    const int kOff = p.kLen ? bz * p.kLen : 0;
    const int Kloc = p.kLen ? p.kLen : p.K;

    const int m0 = blockIdx.x * 128, n0 = blockIdx.y * BN;
    const int lda = p.lda, ldb = p.ldb, ldc = p.ldc;

    const bf16* __restrict__ pAH = p.AH[bi] + (size_t)m0 * lda + kOff;
    const bf16* __restrict__ pAL = p.AL[bi] + (size_t)m0 * lda + kOff;
    const bf16* __restrict__ pBH = p.BH[bi] + (size_t)n0 * ldb + kOff;
    const bf16* __restrict__ pBL = p.BL[bi] + (size_t)n0 * ldb + kOff;
    const float* __restrict__ bias = p.bias[bi];

    const int tid  = threadIdx.x;
    const int lane = tid & 31, wid = tid >> 5;
    const int wm = wid & 3, wn = wid >> 2;

    const uint32_t u0 = s2u(smem);
    const uint32_t aRowOff = (uint32_t)((lane & 15) * ROWB + ((lane & 16) ? 16 : 0));
    const uint32_t bRowOff = (uint32_t)((lane & 7) * ROWB + ((lane & 8) ? 16 : 0));

    float acc[2][NT][4];
#pragma unroll
    for (int mt = 0; mt < 2; mt++)
#pragma unroll
        for (int nt = 0; nt < NT; nt++)
#pragma unroll
            for (int q = 0; q < 4; q++) acc[mt][nt][q] = 0.f;

    uint4 rah, ral, rbh[NBQ], rbl[NBQ];
    const int fRow = tid >> 2;
    const int fC8  = (tid & 3) << 3;
    const int fOff = fRow * ROWB + ((tid & 3) << 4);

    auto loadT = [&](int k0) {
        rah = *reinterpret_cast<const uint4*>(pAH + (size_t)fRow * lda + k0 + fC8);
        ral = *reinterpret_cast<const uint4*>(pAL + (size_t)fRow * lda + k0 + fC8);
#pragma unroll
        for (int q = 0; q < NBQ; q++) {
            int row = fRow + q * 128;
            rbh[q] = *reinterpret_cast<const uint4*>(pBH + (size_t)row * ldb + k0 + fC8);
            rbl[q] = *reinterpret_cast<const uint4*>(pBL + (size_t)row * ldb + k0 + fC8);
        }
    };
    auto storeT = [&](int stage) {
        char* AHs = smem + stage * STAGEB;
        char* ALs = AHs + ATILEB;
        char* BHs = ALs + ATILEB;
        char* BLs = BHs + BTILEB;
        *reinterpret_cast<uint4*>(AHs + fOff) = rah;
        *reinterpret_cast<uint4*>(ALs + fOff) = ral;
#pragma unroll
        for (int q = 0; q < NBQ; q++) {
            *reinterpret_cast<uint4*>(BHs + fOff + q * 128 * ROWB) = rbh[q];
            *reinterpret_cast<uint4*>(BLs + fOff + q * 128 * ROWB) = rbl[q];
        }
    };
    auto compute = [&](int stage) {
        const uint32_t uAH = u0 + (uint32_t)(stage * STAGEB);
        const uint32_t uAL = uAH + ATILEB;
        const uint32_t uBH = uAL + ATILEB;
        const uint32_t uBL = uBH + BTILEB;
#pragma unroll
        for (int ks = 0; ks < 2; ks++) {
            const uint32_t ka = (uint32_t)(ks * 32);
            uint32_t ah[2][4], bh[NT][2];
#pragma unroll
            for (int mt = 0; mt < 2; mt++)
                LDSM4(ah[mt], uAH + (uint32_t)((wm * 32 + mt * 16) * ROWB) + aRowOff + ka);
#pragma unroll
            for (int nt = 0; nt < NT; nt++)
                LDSM2(bh[nt], uBH + (uint32_t)((wn * (NT * 8) + nt * 8) * ROWB) + bRowOff + ka);
#pragma unroll
            for (int mt = 0; mt < 2; mt++)
#pragma unroll
                for (int nt = 0; nt < NT; nt++) mma16816(acc[mt][nt], ah[mt], bh[nt]);
            // pass 2: Ah * Bl, bl loaded on the fly (short live range)
#pragma unroll
            for (int nt = 0; nt < NT; nt++) {
                uint32_t bl2[2];
                LDSM2(bl2, uBL + (uint32_t)((wn * (NT * 8) + nt * 8) * ROWB) + bRowOff + ka);
#pragma unroll
                for (int mt = 0; mt < 2; mt++) mma16816(acc[mt][nt], ah[mt], bl2);
            }
            // pass 3: Al * Bh
#pragma unroll
            for (int mt = 0; mt < 2; mt++) {
                uint32_t alf[4];
                LDSM4(alf, uAL + (uint32_t)((wm * 32 + mt * 16) * ROWB) + aRowOff + ka);
#pragma unroll
                for (int nt = 0; nt < NT; nt++) mma16816(acc[mt][nt], alf, bh[nt]);
            }
        }
    };

    const int niter = Kloc >> 5;
    loadT(0);
    storeT(0);
    if (niter > 1) loadT(32);
    __syncthreads();
    for (int i = 0; i < niter; i++) {
        if (i + 1 < niter) storeT((i + 1) & 1);
        if (i + 2 < niter) loadT((i + 2) << 5);
        compute(i & 1);
        __syncthreads();
    }

    // ---------------- epilogue ----------------
    const int es = p.estore[bz];
    float* __restrict__ C  = p.C[bz];
    bf16* __restrict__ CH = p.CH[bz];
    bf16* __restrict__ CL = p.CL[bz];

    if (es == 3) {
        // transposed split store, staged through smem for coalescing (BN==128 path)
        bf16* sH = reinterpret_cast<bf16*>(smem);
        bf16* sL = reinterpret_cast<bf16*>(smem + BN * 128 * 2);
#pragma unroll
        for (int mt = 0; mt < 2; mt++)
#pragma unroll
            for (int nt = 0; nt < NT; nt++) {
                int ml = wm * 32 + mt * 16 + (lane >> 2);
                int nl = wn * (NT * 8) + nt * 8 + 2 * (lane & 3);
#pragma unroll
                for (int h = 0; h < 2; h++) {
                    int mm = ml + h * 8;
                    float vx = acc[mt][nt][2 * h + 0];
                    float vy = acc[mt][nt][2 * h + 1];
                    if (bias) { vx += bias[n0 + nl]; vy += bias[n0 + nl + 1]; }
                    if (p.act) { vx = fmaxf(vx, 0.f); vy = fmaxf(vy, 0.f); }
                    bf16 hx, lx, hy, ly;
                    split1(vx, hx, lx);
                    split1(vy, hy, ly);
                    sH[nl * 128 + mm] = hx;       sL[nl * 128 + mm] = lx;
                    sH[(nl + 1) * 128 + mm] = hy; sL[(nl + 1) * 128 + mm] = ly;
                }
            }
        __syncthreads();
        const int nchunks = BN * 128 / 8;   // 8 bf16 per 16B chunk
        for (int idx = tid; idx < nchunks; idx += 512) {
            int nrow = idx >> 4;
            int seg  = (idx & 15) * 8;
            *reinterpret_cast<uint4*>(&CH[(size_t)(n0 + nrow) * p.M + m0 + seg]) =
                *reinterpret_cast<uint4*>(&sH[nrow * 128 + seg]);
            *reinterpret_cast<uint4*>(&CL[(size_t)(n0 + nrow) * p.M + m0 + seg]) =
                *reinterpret_cast<uint4*>(&sL[nrow * 128 + seg]);
        }
        return;
    }

    const bf16* __restrict__ mulH = p.mulH;
    const bf16* __restrict__ mulL = p.mulL;

    // stage mask tile into smem with coalesced 16B loads (BN==128; mainloop done)
    bf16* sMH = reinterpret_cast<bf16*>(smem);
    bf16* sML = sMH + 128 * 128;
    if (BN == 128 && mulH) {
        for (int idx = tid; idx < 128 * 16; idx += 512) {
            int r  = idx >> 4;
            int c8 = (idx & 15) << 3;
            *reinterpret_cast<uint4*>(&sMH[r * 128 + c8]) =
                *reinterpret_cast<const uint4*>(&mulH[(size_t)(m0 + r) * ldc + n0 + c8]);
            *reinterpret_cast<uint4*>(&sML[r * 128 + c8]) =
                *reinterpret_cast<const uint4*>(&mulL[(size_t)(m0 + r) * ldc + n0 + c8]);
        }
        __syncthreads();
    }

#pragma unroll
    for (int mt = 0; mt < 2; mt++) {
#pragma unroll
        for (int nt = 0; nt < NT; nt++) {
            int mA = m0 + wm * 32 + mt * 16 + (lane >> 2);
            int n  = n0 + wn * (NT * 8) + nt * 8 + 2 * (lane & 3);
#pragma unroll
            for (int h = 0; h < 2; h++) {
                int mm = mA + h * 8;
                float vx = acc[mt][nt][2 * h + 0];
                float vy = acc[mt][nt][2 * h + 1];
                if (BN == 128 && mulH) {
                    int ml_ = mm - m0, nl_ = n - n0;
                    float2 mh = bf2f2(*reinterpret_cast<const uint32_t*>(&sMH[ml_ * 128 + nl_]));
                    float2 ml2 = bf2f2(*reinterpret_cast<const uint32_t*>(&sML[ml_ * 128 + nl_]));
                    vx *= (mh.x + ml2.x); vy *= (mh.y + ml2.y);
                }
                if (bias) { vx += bias[n]; vy += bias[n + 1]; }
                if (p.act) { vx = fmaxf(vx, 0.f); vy = fmaxf(vy, 0.f); }
                if (es == 0) {
                    *reinterpret_cast<float2*>(&C[(size_t)mm * ldc + n]) = make_float2(vx, vy);
                } else {  // es == 2: split, row-major
                    uint32_t hi, lo;
                    cvt_split2(vx, vy, hi, lo);
                    *reinterpret_cast<uint32_t*>(&CH[(size_t)mm * ldc + n]) = hi;
                    *reinterpret_cast<uint32_t*>(&CL[(size_t)mm * ldc + n]) = lo;
                }
            }
        }
    }
}

// ---- split-K reduce: x = relu(sum part + bias) -> bf16 H/L ----
__global__ void reduce_split_k(const float* __restrict__ bias, bf16* __restrict__ oH,
                               bf16* __restrict__ oL) {
    const int n4 = NND * NHID / 4;
    const size_t S = (size_t)NND * NHID;
    for (int e = blockIdx.x * blockDim.x + threadIdx.x; e < n4; e += gridDim.x * blockDim.x) {
        float4 a = reinterpret_cast<const float4*>(g_part)[e];
        float4 b = reinterpret_cast<const float4*>(g_part + S)[e];
        float4 c = reinterpret_cast<const float4*>(g_part + 2 * S)[e];
        int col = (e * 4) & (NHID - 1);
        float4 v;
        v.x = fmaxf(a.x + b.x + c.x + bias[col + 0], 0.f);
        v.y = fmaxf(a.y + b.y + c.y + bias[col + 1], 0.f);
        v.z = fmaxf(a.z + b.z + c.z + bias[col + 2], 0.f);
        v.w = fmaxf(a.w + b.w + c.w + bias[col + 3], 0.f);
        uint2 h, l;
        split4(v, h, l);
        reinterpret_cast<uint2*>(oH)[e] = h;
        reinterpret_cast<uint2*>(oL)[e] = l;
    }
}

// ---- fused: xt = relu(sum part); xtw2 = xt @ W2  (one warp per row) ----
__global__ void reduce_xtw2_k(const float* __restrict__ W2) {
    int row  = blockIdx.x * 8 + (threadIdx.x >> 5);
    int lane = threadIdx.x & 31;
    if (row >= NND) return;
    const size_t S = (size_t)NND * NHID;
    const float* p0 = g_part + (size_t)row * NHID;
    float acc[8] = {0, 0, 0, 0, 0, 0, 0, 0};
    for (int h = lane; h < NHID; h += 32) {
        float xv = fmaxf(p0[h] + p0[S + h] + p0[2 * S + h], 0.f);
        const float4* wp = reinterpret_cast<const float4*>(&W2[h * 8]);
        float4 wlo = wp[0], whi = wp[1];
        acc[0] = fmaf(xv, wlo.x, acc[0]);
        acc[1] = fmaf(xv, wlo.y, acc[1]);
        acc[2] = fmaf(xv, wlo.z, acc[2]);
        acc[3] = fmaf(xv, wlo.w, acc[3]);
        acc[4] = fmaf(xv, whi.x, acc[4]);
        acc[5] = fmaf(xv, whi.y, acc[5]);
        acc[6] = fmaf(xv, whi.z, acc[6]);
        acc[7] = fmaf(xv, whi.w, acc[7]);
    }
#pragma unroll
    for (int c = 0; c < 8; c++)
#pragma unroll
        for (int off = 16; off; off >>= 1) acc[c] += __shfl_down_sync(0xffffffffu, acc[c], off);
    if (lane == 0) {
#pragma unroll
        for (int c = 0; c < 8; c++) g_xtw2[row * 8 + c] = acc[c];
    }
}

// ---------------- transpose + split ----------------
struct TSArgs {
    const float* in[3];
    bf16* oH[3]; bf16* oL[3];
    int R, C;
};
__global__ void transpose_split_k(const TSArgs p) {
    __shared__ float t[32][33];
    const float* __restrict__ in = p.in[blockIdx.z];
    bf16* __restrict__ oH = p.oH[blockIdx.z];
    bf16* __restrict__ oL = p.oL[blockIdx.z];
    const int R = p.R, C = p.C;
    int c0 = blockIdx.x * 32, r0 = blockIdx.y * 32;
    int x = threadIdx.x, y = threadIdx.y;
#pragma unroll
    for (int i = 0; i < 32; i += 8) t[y + i][x] = in[(size_t)(r0 + y + i) * C + c0 + x];
    __syncthreads();
#pragma unroll
    for (int i = 0; i < 32; i += 8) {
        float v = t[x][y + i];
        bf16 h, l;
        split1(v, h, l);
        oH[(size_t)(c0 + y + i) * R + r0 + x] = h;
        oL[(size_t)(c0 + y + i) * R + r0 + x] = l;
    }
}

// ---------------- elementwise split ----------------
__global__ void split_k(const float* __restrict__ in, bf16* __restrict__ oH,
                        bf16* __restrict__ oL, int n4) {
    for (int e = blockIdx.x * blockDim.x + threadIdx.x; e < n4; e += gridDim.x * blockDim.x) {
        float4 v = reinterpret_cast<const float4*>(in)[e];
        uint2 h, l;
        split4(v, h, l);
        reinterpret_cast<uint2*>(oH)[e] = h;
        reinterpret_cast<uint2*>(oL)[e] = l;
    }
}

// ---- fold: Wfold[l][j][c] = sum_k Wa_l[j,k] * Wagg[l*128+k, c]; bfold = ba@Wagg+bagg
__global__ void fold_k(const float* __restrict__ Wa1, const float* __restrict__ Wa2,
                       const float* __restrict__ Wa3, const float* __restrict__ Wagg,
                       const float* __restrict__ bagg, const float* __restrict__ ba1,
                       const float* __restrict__ ba2, const float* __restrict__ ba3) {
    int j = blockIdx.x * 128 + threadIdx.x;
    int l = blockIdx.y;
    const float* Wa = (l == 0) ? Wa1 : (l == 1) ? Wa2 : Wa3;
    float c0 = 0.f, c1 = 0.f, c2 = 0.f;
    for (int k = 0; k < ADIM; k++) {
        float a = Wa[(size_t)j * ADIM + k];
        const float* wg = &Wagg[(l * ADIM + k) * 3];
        c0 = fmaf(a, wg[0], c0);
        c1 = fmaf(a, wg[1], c1);
        c2 = fmaf(a, wg[2], c2);
    }
    g_wfold[(l * 3 + 0) * NND + j] = c0;
    g_wfold[(l * 3 + 1) * NND + j] = c1;
    g_wfold[(l * 3 + 2) * NND + j] = c2;
    if (blockIdx.x == 0 && l == 0 && threadIdx.x < 3) {
        int c = threadIdx.x;
        float b = bagg[c];
        for (int k = 0; k < ADIM; k++) {
            b += ba1[k] * Wagg[k * 3 + c];
            b += ba2[k] * Wagg[(ADIM + k) * 3 + c];
            b += ba3[k] * Wagg[(2 * ADIM + k) * 3 + c];
        }
        g_bfold[c] = b;
    }
}

// ---- gemv+gate: z4[r,c] = sum_l sum_j adj_l[r,j]*Wfold[l][j][c] + bfold; nz=softmax
#define GV_ROWS 32
#define GV_CH 512
__device__ __forceinline__ float dot4(float4 a, float4 b) {
    return a.x * b.x + a.y * b.y + a.z * b.z + a.w * b.w;
}
__global__ void gemv_nz_k(const float* __restrict__ a0, const float* __restrict__ a1,
                          const float* __restrict__ a2, float* __restrict__ out_nz,
                          int write_out) {
    __shared__ float sw[9][GV_CH];
    const int tid = threadIdx.x;
    const int lane = tid & 31, warp = tid >> 5;
    const int rbase = blockIdx.x * GV_ROWS + warp * 4;
    float s[4][3];
#pragma unroll
    for (int r = 0; r < 4; r++)
#pragma unroll
        for (int c = 0; c < 3; c++) s[r][c] = 0.f;

    for (int ch = 0; ch < NND; ch += GV_CH) {
        __syncthreads();
        for (int idx = tid; idx < 9 * GV_CH; idx += 256) {
            int t = idx / GV_CH, j = idx % GV_CH;
            sw[t][j] = g_wfold[(size_t)t * NND + ch + j];
        }
        __syncthreads();
#pragma unroll 2
        for (int j = lane * 4; j < GV_CH; j += 128) {
            float4 wv[9];
#pragma unroll
            for (int t = 0; t < 9; t++) wv[t] = *reinterpret_cast<const float4*>(&sw[t][j]);
#pragma unroll
            for (int r = 0; r < 4; r++) {
                size_t off = (size_t)(rbase + r) * NND + ch + j;
                float4 v0 = *reinterpret_cast<const float4*>(a0 + off);
                float4 v1 = *reinterpret_cast<const float4*>(a1 + off);
                float4 v2 = *reinterpret_cast<const float4*>(a2 + off);
                s[r][0] += dot4(v0, wv[0]) + dot4(v1, wv[3]) + dot4(v2, wv[6]);
                s[r][1] += dot4(v0, wv[1]) + dot4(v1, wv[4]) + dot4(v2, wv[7]);
                s[r][2] += dot4(v0, wv[2]) + dot4(v1, wv[5]) + dot4(v2, wv[8]);
            }
        }
    }
#pragma unroll
    for (int r = 0; r < 4; r++)
#pragma unroll
        for (int c = 0; c < 3; c++) {
            float v = s[r][c];
#pragma unroll
            for (int off = 16; off; off >>= 1) v += __shfl_down_sync(0xffffffffu, v, off);
            s[r][c] = v;
        }
    if (lane == 0) {
#pragma unroll
        for (int r = 0; r < 4; r++) {
            int row = rbase + r;
            float z0 = s[r][0] + g_bfold[0];
            float z1 = s[r][1] + g_bfold[1];
            float z2 = s[r][2] + g_bfold[2];
            float mx = fmaxf(z0, fmaxf(z1, z2));
            float e0 = expf(z0 - mx), e1 = expf(z1 - mx), e2 = expf(z2 - mx);
            float inv = 1.f / (e0 + e1 + e2);
            e0 *= inv; e1 *= inv; e2 *= inv;
            g_nzT[0 * NND + row] = e0;
            g_nzT[1 * NND + row] = e1;
            g_nzT[2 * NND + row] = e2;
            if (write_out) {
                out_nz[row * 3 + 0] = e0;
                out_nz[row * 3 + 1] = e1;
                out_nz[row * 3 + 2] = e2;
            }
        }
    }
}

// ---- adj = col-weighted mix; emit bf16 H/L only, 8 elems/iter ----
__global__ void build_adj_k(const float* __restrict__ a0, const float* __restrict__ a1,
                            const float* __restrict__ a2) {
    const size_t total8 = (size_t)NND * NND / 8;
    for (size_t e = (size_t)blockIdx.x * blockDim.x + threadIdx.x; e < total8;
         e += (size_t)gridDim.x * blockDim.x) {
        size_t off = e * 8;
        int j = (int)(off % NND);
#pragma unroll
        for (int u = 0; u < 2; u++) {
            size_t o = off + u * 4;
            int jj = j + u * 4;
            float4 w0 = *reinterpret_cast<const float4*>(&g_nzT[jj]);
            float4 w1 = *reinterpret_cast<const float4*>(&g_nzT[NND + jj]);
            float4 w2 = *reinterpret_cast<const float4*>(&g_nzT[2 * NND + jj]);
            float4 x0 = *reinterpret_cast<const float4*>(a0 + o);
            float4 x1 = *reinterpret_cast<const float4*>(a1 + o);
            float4 x2 = *reinterpret_cast<const float4*>(a2 + o);
            float4 r;
            r.x = w0.x * x0.x + w1.x * x1.x + w2.x * x2.x;
            r.y = w0.y * x0.y + w1.y * x1.y + w2.y * x2.y;
            r.z = w0.z * x0.z + w1.z * x1.z + w2.z * x2.z;
            r.w = w0.w * x0.w + w1.w * x1.w + w2.w * x2.w;
            uint2 h, l;
            split4(r, h, l);
            *reinterpret_cast<uint2*>(&g_adjH[o]) = h;
            *reinterpret_cast<uint2*>(&g_adjL[o]) = l;
        }
    }
}

// ---- per-row softmax over 6144-wide fp32 logits; emit bf16 split ----
__global__ void attn_softmax_k() {
    const int row = blockIdx.x;
    const float* __restrict__ ptr = &g_att[(size_t)row * NND];
    const int tid  = threadIdx.x;
    const int lane = tid & 31, warp = tid >> 5;
    float4 v[6];
    float mx = -3.4e38f;
#pragma unroll
    for (int l = 0; l < 6; l++) {
        v[l] = *reinterpret_cast<const float4*>(&ptr[(tid + l * 256) * 4]);
        mx = fmaxf(mx, fmaxf(fmaxf(v[l].x, v[l].y), fmaxf(v[l].z, v[l].w)));
    }
    __shared__ float sm[8], ss[8];
#pragma unroll
    for (int off = 16; off; off >>= 1) mx = fmaxf(mx, __shfl_xor_sync(0xffffffffu, mx, off));
    if (lane == 0) sm[warp] = mx;
    __syncthreads();
    float bm = fmaxf(fmaxf(fmaxf(sm[0], sm[1]), fmaxf(sm[2], sm[3])),
                     fmaxf(fmaxf(sm[4], sm[5]), fmaxf(sm[6], sm[7])));
    float sum = 0.f;
#pragma unroll
    for (int l = 0; l < 6; l++) {
        v[l].x = expf(v[l].x - bm);
        v[l].y = expf(v[l].y - bm);
        v[l].z = expf(v[l].z - bm);
        v[l].w = expf(v[l].w - bm);
        sum += v[l].x + v[l].y + v[l].z + v[l].w;
    }
#pragma unroll
    for (int off = 16; off; off >>= 1) sum += __shfl_xor_sync(0xffffffffu, sum, off);
    if (lane == 0) ss[warp] = sum;
    __syncthreads();
    float tot = ss[0] + ss[1] + ss[2] + ss[3] + ss[4] + ss[5] + ss[6] + ss[7];
    float scale = 1.f / tot;
#pragma unroll
    for (int l = 0; l < 6; l++) {
        v[l].x *= scale; v[l].y *= scale; v[l].z *= scale; v[l].w *= scale;
        uint2 h, lo;
        split4(v[l], h, lo);
        size_t off = (size_t)row * NND + (tid + l * 256) * 4;
        *reinterpret_cast<uint2*>(&g_attH[off]) = h;
        *reinterpret_cast<uint2*>(&g_attL[off]) = lo;
    }
}

// ---------------- z = (adjH+adjL) @ xtw2 + b2 ; out = softmax(z). 8 rows/CTA ----
__global__ void final_k(const float* __restrict__ b2, float* __restrict__ out) {
    const int r0  = blockIdx.x * 8;
    const int tid = threadIdx.x;
    float acc[8][8];
#pragma unroll
    for (int r = 0; r < 8; r++)
#pragma unroll
        for (int c = 0; c < 8; c++) acc[r][c] = 0.f;

    for (int j4 = tid; j4 < NND / 4; j4 += 256) {
        float4 w[8];
        const float4* wp = reinterpret_cast<const float4*>(&g_xtw2[(size_t)j4 * 32]);
#pragma unroll
        for (int q = 0; q < 8; q++) w[q] = wp[q];
#pragma unroll
        for (int r = 0; r < 8; r++) {
            size_t off = (size_t)(r0 + r) * NND + j4 * 4;
            uint2 hz = *reinterpret_cast<const uint2*>(&g_adjH[off]);
            uint2 lz = *reinterpret_cast<const uint2*>(&g_adjL[off]);
            float2 h0 = bf2f2(hz.x), h1 = bf2f2(hz.y);
            float2 l0 = bf2f2(lz.x), l1 = bf2f2(lz.y);
            float av[4] = {h0.x + l0.x, h0.y + l0.y, h1.x + l1.x, h1.y + l1.y};
#pragma unroll
            for (int q = 0; q < 4; q++) {
                acc[r][0] = fmaf(av[q], w[2 * q].x, acc[r][0]);
                acc[r][1] = fmaf(av[q], w[2 * q].y, acc[r][1]);
                acc[r][2] = fmaf(av[q], w[2 * q].z, acc[r][2]);
                acc[r][3] = fmaf(av[q], w[2 * q].w, acc[r][3]);
                acc[r][4] = fmaf(av[q], w[2 * q + 1].x, acc[r][4]);
                acc[r][5] = fmaf(av[q], w[2 * q + 1].y, acc[r][5]);
                acc[r][6] = fmaf(av[q], w[2 * q + 1].z, acc[r][6]);
                acc[r][7] = fmaf(av[q], w[2 * q + 1].w, acc[r][7]);
            }
        }
    }

    __shared__ float sred[8][64];
    const int lane = tid & 31, warp = tid >> 5;
#pragma unroll
    for (int r = 0; r < 8; r++)
#pragma unroll
        for (int c = 0; c < 8; c++) {
            float vv = acc[r][c];
#pragma unroll
            for (int off = 16; off; off >>= 1) vv += __shfl_down_sync(0xffffffffu, vv, off);
            if (lane == 0) sred[warp][r * 8 + c] = vv;
        }
    __syncthreads();
    if (tid < 64) {
        float v = 0.f;
#pragma unroll
        for (int w = 0; w < 8; w++) v += sred[w][tid];
        int c = tid & 7;
        v += b2[c];
        float mx = v;
#pragma unroll
        for (int off = 4; off; off >>= 1) mx = fmaxf(mx, __shfl_xor_sync(0xffffffffu, mx, off, 8));
        float e = expf(v - mx);
        float s = e;
#pragma unroll
        for (int off = 4; off; off >>= 1) s += __shfl_xor_sync(0xffffffffu, s, off, 8);
        out[(size_t)(r0 + (tid >> 3)) * 8 + c] = e / s;
    }
}

// ---------------- host side ----------------
template <typename T>
static T* symaddr(const void* sym) {
    void* p = nullptr;
    cudaGetSymbolAddress(&p, sym);
    return (T*)p;
}

#define GSMEM128 (2 * (2 * ATILEB + 2 * 128 * ROWB))   // 81920
#define GSMEM256 (2 * (2 * ATILEB + 2 * 256 * ROWB))   // 122880

extern "C" void kernel_launch(void* const* d_in, const int* in_sizes, int n_in,
                              void* d_out, int out_size) {
    const float* adj0 = (const float*)d_in[0];
    const float* adj1 = (const float*)d_in[1];
    const float* adj2 = (const float*)d_in[2];
    const float* feats = (const float*)d_in[3];
    const float* Wa1 = (const float*)d_in[4];
    const float* ba1 = (const float*)d_in[5];
    const float* Wa2 = (const float*)d_in[6];
    const float* ba2 = (const float*)d_in[7];
    const float* Wa3 = (const float*)d_in[8];
    const float* ba3 = (const float*)d_in[9];
    const float* Wagg = (const float*)d_in[10];
    const float* bagg = (const float*)d_in[11];
    const float* W1 = (const float*)d_in[12];
    const float* b1 = (const float*)d_in[13];
    const float* Wq = (const float*)d_in[14];
    const float* bq = (const float*)d_in[15];
    const float* Wk = (const float*)d_in[16];
    const float* bk = (const float*)d_in[17];
    const float* Wv = (const float*)d_in[18];
    const float* bv = (const float*)d_in[19];
    const float* W2 = (const float*)d_in[20];
    const float* b2 = (const float*)d_in[21];
    float* out = (float*)d_out;

    float* attp  = symaddr<float>(g_att);
    float* partp = symaddr<float>(g_part);
    bf16* adjH = symaddr<bf16>(g_adjH);   bf16* adjL = symaddr<bf16>(g_adjL);
    bf16* attH = symaddr<bf16>(g_attH);   bf16* attL = symaddr<bf16>(g_attL);
    bf16* ftH  = symaddr<bf16>(g_featsH); bf16* ftL  = symaddr<bf16>(g_featsL);
    bf16* W1TH = symaddr<bf16>(g_W1TH);   bf16* W1TL = symaddr<bf16>(g_W1TL);
    bf16* WqTH = symaddr<bf16>(g_WqTH);   bf16* WqTL = symaddr<bf16>(g_WqTL);
    bf16* WkTH = symaddr<bf16>(g_WkTH);   bf16* WkTL = symaddr<bf16>(g_WkTL);
    bf16* WvTH = symaddr<bf16>(g_WvTH);   bf16* WvTL = symaddr<bf16>(g_WvTL);
    bf16* fW1TH = symaddr<bf16>(g_fW1TH); bf16* fW1TL = symaddr<bf16>(g_fW1TL);
    bf16* xH   = symaddr<bf16>(g_xH);     bf16* xL   = symaddr<bf16>(g_xL);
    bf16* QH   = symaddr<bf16>(g_QH);     bf16* QL   = symaddr<bf16>(g_QL);
    bf16* KHp  = symaddr<bf16>(g_KHb);    bf16* KLp  = symaddr<bf16>(g_KLb);
    bf16* VTH  = symaddr<bf16>(g_VTH);    bf16* VTL  = symaddr<bf16>(g_VTL);

    cudaFuncSetAttribute(mma_gemm<128>, cudaFuncAttributeMaxDynamicSharedMemorySize, GSMEM128);
    cudaFuncSetAttribute(mma_gemm<256>, cudaFuncAttributeMaxDynamicSharedMemorySize, GSMEM256);

    int write_nz = (out_size >= NND * (NCLASS + 3)) ? 1 : 0;
    const size_t PS = (size_t)NND * NHID;

    // 0: feats split
    split_k<<<592, 256>>>(feats, ftH, ftL, NND * NFEAT / 4);
    // 1: W1 transpose+split
    {
        TSArgs t{};
        t.in[0] = W1; t.oH[0] = W1TH; t.oL[0] = W1TL; t.R = NFEAT; t.C = NHID;
        transpose_split_k<<<dim3(NHID / 32, NFEAT / 32, 1), dim3(32, 8)>>>(t);
    }
    // 2: fold
    fold_k<<<dim3(NND / 128, 3), 128>>>(Wa1, Wa2, Wa3, Wagg, bagg, ba1, ba2, ba3);

    // 3: L4: fW1^T(split) = (feats @ W1)^T   <-- profiled launch
    {
        GArgs a{};
        a.AH[0] = ftH; a.AL[0] = ftL;
        a.BH[0] = W1TH; a.BL[0] = W1TL;
        a.CH[0] = fW1TH; a.CL[0] = fW1TL;
        a.M = NND; a.N = NHID; a.K = NFEAT; a.lda = NFEAT; a.ldb = NFEAT; a.ldc = NHID;
        a.estore[0] = 3;
        mma_gemm<128><<<dim3(48, 2, 1), 512, GSMEM128>>>(a);
    }

    // 4: gemv + gate softmax -> nz
    gemv_nz_k<<<NND / GV_ROWS, 256>>>(adj0, adj1, adj2, out + (size_t)NND * NCLASS, write_nz);
    // 5: Wq/Wk/Wv transpose+split (batched)
    {
        TSArgs t{};
        t.in[0] = Wq; t.in[1] = Wk; t.in[2] = Wv;
        t.oH[0] = WqTH; t.oH[1] = WkTH; t.oH[2] = WvTH;
        t.oL[0] = WqTL; t.oL[1] = WkTL; t.oL[2] = WvTL;
        t.R = NHID; t.C = NHID;
        transpose_split_k<<<dim3(NHID / 32, NHID / 32, 3), dim3(32, 8)>>>(t);
    }
    // 6: fused adjacency (bf16 H/L)
    build_adj_k<<<1184, 256>>>(adj0, adj1, adj2);

    // 7: L5 split-K (BN=256, single y-block -> A read once)
    {
        GArgs a{};
        a.AH[0] = adjH; a.AL[0] = adjL;
        a.BH[0] = fW1TH; a.BL[0] = fW1TL;
        a.C[0] = partp; a.C[1] = partp + PS; a.C[2] = partp + 2 * PS;
        a.M = NND; a.N = NHID; a.K = NND; a.lda = NND; a.ldb = NND; a.ldc = NHID;
        a.kLen = NND / 3;
        a.estore[0] = a.estore[1] = a.estore[2] = 0;
        mma_gemm<256><<<dim3(48, 1, 3), 512, GSMEM256>>>(a);
    }
    // 8: reduce -> x (split)
    reduce_split_k<<<1536, 256>>>(b1, xH, xL);

    // 9: L6: Q,K (split); V (split transposed, staged)
    {
        GArgs a{};
        a.AH[0] = a.AH[1] = a.AH[2] = xH;
        a.AL[0] = a.AL[1] = a.AL[2] = xL;
        a.BH[0] = WqTH; a.BH[1] = WkTH; a.BH[2] = WvTH;
        a.BL[0] = WqTL; a.BL[1] = WkTL; a.BL[2] = WvTL;
        a.CH[0] = QH; a.CL[0] = QL;
        a.CH[1] = KHp; a.CL[1] = KLp;
        a.CH[2] = VTH; a.CL[2] = VTL;
        a.bias[0] = bq; a.bias[1] = bk; a.bias[2] = bv;
        a.M = NND; a.N = NHID; a.K = NHID; a.lda = NHID; a.ldb = NHID; a.ldc = NHID;
        a.estore[0] = 2; a.estore[1] = 2; a.estore[2] = 3;
        mma_gemm<128><<<dim3(48, 2, 3), 512, GSMEM128>>>(a);
    }

    // 10: L7: A_tilde = (adjH+adjL) * (Q @ K^T)  (fp32 logits; mask staged via smem)
    {
        GArgs a{};
        a.AH[0] = QH; a.AL[0] = QL;
        a.BH[0] = KHp; a.BL[0] = KLp;
        a.C[0] = attp;
        a.mulH = adjH; a.mulL = adjL;
        a.M = NND; a.N = NND; a.K = NHID; a.lda = NHID; a.ldb = NHID; a.ldc = NND;
        a.estore[0] = 0;
        mma_gemm<128><<<dim3(48, 48, 1), 512, GSMEM128>>>(a);
    }

    // 11: row softmax -> att split
    attn_softmax_k<<<NND, 256>>>();

    // 12: L9 split-K (BN=256)
    {
        GArgs a{};
        a.AH[0] = attH; a.AL[0] = attL;
        a.BH[0] = VTH; a.BL[0] = VTL;
        a.C[0] = partp; a.C[1] = partp + PS; a.C[2] = partp + 2 * PS;
        a.M = NND; a.N = NHID; a.K = NND; a.lda = NND; a.ldb = NND; a.ldc = NHID;
        a.kLen = NND / 3;
        a.estore[0] = a.estore[1] = a.estore[2] = 0;
        mma_gemm<256><<<dim3(48, 1, 3), 512, GSMEM256>>>(a);
    }

    // 13: fused reduce(relu) + @W2
    reduce_xtw2_k<<<768, 256>>>(W2);
    // 14: final
    final_k<<<768, 256>>>(b2, out);
}